// round 5
// baseline (speedup 1.0000x reference)
#include <cuda_runtime.h>

#define Bb 32
#define Nn 1024
#define Hh 128
#define THREADS 256
#define WARPS 8
#define RPT 4
#define ROWS_PER_BLOCK (WARPS * RPT)  // 32
#define GRIDX (Nn / ROWS_PER_BLOCK)   // 32

__device__ float g_prm[9];    // u0..2, au, v0..2, av, kd (pre-scaled by log2 e)
__device__ int   g_mask_byte;
__device__ int   g_cnt[Bb];   // per-batch tickets (reset after use)

__device__ __forceinline__ float ex2f_(float x) {
    float y; asm("ex2.approx.ftz.f32 %0, %1;" : "=f"(y) : "f"(x)); return y;
}
__device__ __forceinline__ float sqrtf_(float x) {
    float y; asm("sqrt.approx.ftz.f32 %0, %1;" : "=f"(y) : "f"(x)); return y;
}
__device__ __forceinline__ bool mask_at(const void* m, int idx, int isByte) {
    if (isByte) return ((const unsigned char*)m)[idx] != 0;
    return ((const int*)m)[idx] != 0;
}

// One softmax term; used by loop AND diagonal correction -> bit-identical.
__device__ __forceinline__ float pair_term(float2 AC, float4 P, float cbw,
                                           float pxi, float pyi, float pzi,
                                           float sqi, float nrm) {
    float t = fmaf(P.z, pzi, P.w);
    t = fmaf(P.y, pyi, t);
    t = fmaf(P.x, pxi, t);
    float d2 = fmaxf(sqi + t, 1e-12f);
    float dist = sqrtf_(d2);
    float s = fmaf(nrm, AC.x, AC.y);
    s = fmaf(cbw, dist, s);
    return ex2f_(s);
}

// ---------------------------------------------------------------------------
__global__ __launch_bounds__(1024)
void setup_kernel(const unsigned int* __restrict__ nm,
                  const float* __restrict__ lin1_w,
                  const float* __restrict__ lin1_b,
                  const float* __restrict__ wp,
                  const float* __restrict__ bp,
                  const float* __restrict__ wd,
                  const float* __restrict__ wc) {
    int any = 0;
    for (int k = threadIdx.x; k < (Bb * Nn) / 4; k += 1024)
        if (nm[k] > 1u) any = 1;
    int r = __syncthreads_or(any);
    if (threadIdx.x == 0) g_mask_byte = r ? 1 : 0;

    if (threadIdx.x < 32) {
        const float L2E = 1.4426950408889634f;
        int lane = threadIdx.x;
        float u0 = 0.f, u1 = 0.f, u2 = 0.f, au = 0.f;
        float v0 = 0.f, v1 = 0.f, v2 = 0.f, av = 0.f, kd = 0.f;
        for (int h = lane; h < Hh; h += 32) {
            float w1h = wc[h];
            float w2h = wc[Hh + h];
            float a = lin1_w[h] * w1h;
            float c = lin1_b[h] * w1h;
            float wp0 = wp[h * 3 + 0], wp1 = wp[h * 3 + 1], wp2 = wp[h * 3 + 2];
            u0 = fmaf(a, wp0, u0); u1 = fmaf(a, wp1, u1); u2 = fmaf(a, wp2, u2);
            au = fmaf(a, bp[h], au);
            v0 = fmaf(c, wp0, v0); v1 = fmaf(c, wp1, v1); v2 = fmaf(c, wp2, v2);
            av = fmaf(c, bp[h], av);
            kd = fmaf(wd[h], w2h, kd);
        }
        #pragma unroll
        for (int o = 16; o > 0; o >>= 1) {
            u0 += __shfl_xor_sync(0xFFFFFFFFu, u0, o);
            u1 += __shfl_xor_sync(0xFFFFFFFFu, u1, o);
            u2 += __shfl_xor_sync(0xFFFFFFFFu, u2, o);
            au += __shfl_xor_sync(0xFFFFFFFFu, au, o);
            v0 += __shfl_xor_sync(0xFFFFFFFFu, v0, o);
            v1 += __shfl_xor_sync(0xFFFFFFFFu, v1, o);
            v2 += __shfl_xor_sync(0xFFFFFFFFu, v2, o);
            av += __shfl_xor_sync(0xFFFFFFFFu, av, o);
            kd += __shfl_xor_sync(0xFFFFFFFFu, kd, o);
        }
        if (lane == 0) {
            g_prm[0] = u0 * L2E; g_prm[1] = u1 * L2E; g_prm[2] = u2 * L2E; g_prm[3] = au * L2E;
            g_prm[4] = v0 * L2E; g_prm[5] = v1 * L2E; g_prm[6] = v2 * L2E; g_prm[7] = av * L2E;
            g_prm[8] = kd * L2E;
        }
    }
}

// ---------------------------------------------------------------------------
__global__ __launch_bounds__(THREADS, 4)
void attn_kernel(const float* __restrict__ pos,
                 const void* __restrict__ node_mask,
                 const float* __restrict__ p,
                 const void* __restrict__ pharma,
                 const float* __restrict__ lin1_w,
                 const float* __restrict__ lin1_b,
                 const float* __restrict__ lin2_w,
                 const float* __restrict__ lin2_b,
                 float* __restrict__ out) {
    __shared__ float2 s_AC[Nn];
    __shared__ float4 s_P[Nn];
    __shared__ float4 s_Q[Nn];
    __shared__ int    s_rows[ROWS_PER_BLOCK];
    __shared__ int    s_np;
    __shared__ float  s_red[WARPS];
    __shared__ float  s_mean[3];
    __shared__ int    s_tk;

    const int b = blockIdx.y;
    const int tid = threadIdx.x;
    const int isB = g_mask_byte;

    const float u0 = g_prm[0], u1 = g_prm[1], u2 = g_prm[2], au = g_prm[3];
    const float v0 = g_prm[4], v1 = g_prm[5], v2 = g_prm[6], av = g_prm[7];
    const float kdL = g_prm[8];

    const float* posb = pos + (size_t)b * Nn * 3;
    const float* pb   = p   + (size_t)b * Nn * 3;

    for (int j = tid; j < Nn; j += THREADS) {
        float qx = posb[j * 3 + 0], qy = posb[j * 3 + 1], qz = posb[j * 3 + 2];
        float A = fmaf(qx, u0, fmaf(qy, u1, fmaf(qz, u2, au)));
        float C = fmaf(qx, v0, fmaf(qy, v1, fmaf(qz, v2, av)));
        s_AC[j] = make_float2(A, C);
        float px = pb[j * 3 + 0], py = pb[j * 3 + 1], pz = pb[j * 3 + 2];
        float sq = fmaf(px, px, fmaf(py, py, pz * pz));
        s_P[j] = make_float4(-2.f * px, -2.f * py, -2.f * pz, sq);
        float cb = mask_at(pharma, b * Nn + j, isB) ? kdL : 0.f;
        s_Q[j] = make_float4(qx, qy, qz, cb);
    }
    __syncthreads();

    // Partition this block's 32 rows: pharma-gated rows first (one ballot).
    if (tid < 32) {
        int row = blockIdx.x * ROWS_PER_BLOCK + tid;
        bool ph = (s_Q[row].w != 0.f);
        unsigned m = __ballot_sync(0xFFFFFFFFu, ph);
        int np = __popc(m);
        unsigned below = m & ((tid == 31) ? 0x7FFFFFFFu : ((1u << tid) - 1u));
        int pos_;
        if (ph) pos_ = __popc(below);
        else    pos_ = np + (tid - __popc(below));
        s_rows[pos_] = row;
        if (tid == 0) s_np = np;
    }
    __syncthreads();

    const int w = tid >> 5;
    const int lane = tid & 31;
    const int np = s_np;
    const int base = w * RPT;
    // class: 0 = all pharma, 2 = all cheap, 1 = mixed
    const int cls = (base + RPT <= np) ? 0 : ((base >= np) ? 2 : 1);

    // hot-loop register state only (ir/cbw re-derived in epilogue from smem)
    float pxi[RPT], pyi[RPT], pzi[RPT], sqi[RPT], nrm[RPT], rgf[RPT];
    float sum[RPT], cx[RPT], cy[RPT], cz[RPT];
    #pragma unroll
    for (int r = 0; r < RPT; r++) {
        int row = s_rows[base + r];
        float4 P = s_P[row];
        pxi[r] = -0.5f * P.x; pyi[r] = -0.5f * P.y; pzi[r] = -0.5f * P.z;
        sqi[r] = P.w;
        float4 Q = s_Q[row];
        nrm[r] = sqrtf(fmaf(Q.x, Q.x, fmaf(Q.y, Q.y, Q.z * Q.z)));
        rgf[r] = (base + r < np) ? 1.f : 0.f;
        sum[r] = 0.f; cx[r] = 0.f; cy[r] = 0.f; cz[r] = 0.f;
    }

    if (cls == 0) {
        #pragma unroll 4
        for (int jj = 0; jj < Nn / 32; jj++) {
            const int j = jj * 32 + lane;
            const float2 AC = s_AC[j];
            const float4 P  = s_P[j];
            const float4 Q  = s_Q[j];
            #pragma unroll
            for (int r = 0; r < RPT; r++) {
                float e = pair_term(AC, P, Q.w, pxi[r], pyi[r], pzi[r], sqi[r], nrm[r]);
                sum[r] += e;
                cx[r] = fmaf(e, Q.x, cx[r]);
                cy[r] = fmaf(e, Q.y, cy[r]);
                cz[r] = fmaf(e, Q.z, cz[r]);
            }
        }
    } else if (cls == 2) {
        #pragma unroll 4
        for (int jj = 0; jj < Nn / 32; jj++) {
            const int j = jj * 32 + lane;
            const float2 AC = s_AC[j];
            const float4 Q  = s_Q[j];
            #pragma unroll
            for (int r = 0; r < RPT; r++) {
                float e = ex2f_(fmaf(nrm[r], AC.x, AC.y));
                sum[r] += e;
                cx[r] = fmaf(e, Q.x, cx[r]);
                cy[r] = fmaf(e, Q.y, cy[r]);
                cz[r] = fmaf(e, Q.z, cz[r]);
            }
        }
    } else {
        #pragma unroll 4
        for (int jj = 0; jj < Nn / 32; jj++) {
            const int j = jj * 32 + lane;
            const float2 AC = s_AC[j];
            const float4 P  = s_P[j];
            const float4 Q  = s_Q[j];
            #pragma unroll
            for (int r = 0; r < RPT; r++) {
                float cb = Q.w * rgf[r];
                float e = pair_term(AC, P, cb, pxi[r], pyi[r], pzi[r], sqi[r], nrm[r]);
                sum[r] += e;
                cx[r] = fmaf(e, Q.x, cx[r]);
                cy[r] = fmaf(e, Q.y, cy[r]);
                cz[r] = fmaf(e, Q.z, cz[r]);
            }
        }
    }

    // per-row MLP: new_norm
    float nnv[RPT];
    #pragma unroll
    for (int r = 0; r < RPT; r++) {
        float nn = 0.f;
        #pragma unroll
        for (int h = lane; h < Hh; h += 32) {
            float hid = fmaf(nrm[r], lin1_w[h], lin1_b[h]);
            nn = fmaf(fmaxf(hid, 0.f), lin2_w[h], nn);
        }
        nnv[r] = nn;
    }

    #pragma unroll
    for (int r = 0; r < RPT; r++) {
        #pragma unroll
        for (int o = 16; o > 0; o >>= 1) {
            sum[r] += __shfl_xor_sync(0xFFFFFFFFu, sum[r], o);
            cx[r]  += __shfl_xor_sync(0xFFFFFFFFu, cx[r], o);
            cy[r]  += __shfl_xor_sync(0xFFFFFFFFu, cy[r], o);
            cz[r]  += __shfl_xor_sync(0xFFFFFFFFu, cz[r], o);
            nnv[r] += __shfl_xor_sync(0xFFFFFFFFu, nnv[r], o);
        }
    }

    const float l2b = lin2_b[0];
    #pragma unroll
    for (int r = 0; r < RPT; r++) {
        if (lane == r) {
            int i = s_rows[base + r];
            int gi = b * Nn + i;
            float4 Q = s_Q[i];
            float S = sum[r], X = cx[r], Y = cy[r], Z = cz[r];
            if (cls != 2) {
                // exact diagonal fix: remove loop's j==i term, add dist-free term
                float cbw = Q.w * rgf[r];
                float e_wrong = pair_term(s_AC[i], s_P[i], cbw,
                                          pxi[r], pyi[r], pzi[r], sqi[r], nrm[r]);
                float e_right = ex2f_(fmaf(nrm[r], s_AC[i].x, s_AC[i].y));
                float d = e_right - e_wrong;
                S += d; X = fmaf(d, Q.x, X); Y = fmaf(d, Q.y, Y); Z = fmaf(d, Q.z, Z);
            }
            float f = mask_at(node_mask, gi, isB)
                        ? (nnv[r] + l2b) / (S * (nrm[r] + 1e-5f)) : 0.f;
            out[gi * 3 + 0] = Q.x * X * f;
            out[gi * 3 + 1] = Q.y * Y * f;
            out[gi * 3 + 2] = Q.z * Z * f;
        }
    }

    // fused per-batch mean subtraction (last block of batch)
    __threadfence();
    __syncthreads();
    if (tid == 0) s_tk = atomicAdd(&g_cnt[b], 1);
    __syncthreads();
    if (s_tk == GRIDX - 1) {
        __threadfence();
        float ax = 0.f, ay = 0.f, az = 0.f;
        for (int n = tid; n < Nn; n += THREADS) {
            const float* o = out + ((size_t)b * Nn + n) * 3;
            ax += o[0]; ay += o[1]; az += o[2];
        }
        float* comps[3] = {&ax, &ay, &az};
        #pragma unroll
        for (int c = 0; c < 3; c++) {
            float v = *comps[c];
            #pragma unroll
            for (int o = 16; o > 0; o >>= 1) v += __shfl_xor_sync(0xFFFFFFFFu, v, o);
            if (lane == 0) s_red[w] = v;
            __syncthreads();
            if (tid == 0) {
                float t = 0.f;
                #pragma unroll
                for (int k = 0; k < WARPS; k++) t += s_red[k];
                s_mean[c] = t * (1.f / Nn);
            }
            __syncthreads();
        }
        float mx = s_mean[0], my = s_mean[1], mz = s_mean[2];
        for (int n = tid; n < Nn; n += THREADS) {
            float* o = out + ((size_t)b * Nn + n) * 3;
            o[0] -= mx; o[1] -= my; o[2] -= mz;
        }
        if (tid == 0) atomicExch(&g_cnt[b], 0);
    }
}

extern "C" void kernel_launch(void* const* d_in, const int* in_sizes, int n_in,
                              void* d_out, int out_size) {
    const float* pos       = (const float*)d_in[0];
    const void*  node_mask = d_in[1];
    const float* p         = (const float*)d_in[2];
    const void*  pharma    = d_in[3];
    const float* lin1_w    = (const float*)d_in[4];
    const float* lin1_b    = (const float*)d_in[5];
    const float* lin2_w    = (const float*)d_in[6];
    const float* lin2_b    = (const float*)d_in[7];
    const float* wp        = (const float*)d_in[8];
    const float* bp        = (const float*)d_in[9];
    const float* wd        = (const float*)d_in[10];
    const float* wc        = (const float*)d_in[12];

    setup_kernel<<<1, 1024>>>((const unsigned int*)node_mask,
                              lin1_w, lin1_b, wp, bp, wd, wc);

    dim3 grid(GRIDX, Bb);
    attn_kernel<<<grid, THREADS>>>(pos, node_mask, p, pharma,
                                   lin1_w, lin1_b, lin2_w, lin2_b,
                                   (float*)d_out);
}

// round 6
// speedup vs baseline: 1.0530x; 1.0530x over previous
#include <cuda_runtime.h>

#define Bb 32
#define Nn 1024
#define Hh 128
#define THREADS 256
#define WARPS 8
#define RPT 4
#define ROWS_PER_BLOCK (WARPS * RPT)  // 32
#define GRIDX (Nn / ROWS_PER_BLOCK)   // 32

__device__ float g_prm[9];    // u0..2, au, v0..2, av, kd (pre-scaled by log2 e)
__device__ int   g_mask_byte;
__device__ int   g_cnt[Bb];   // per-batch tickets (reset after use)

__device__ __forceinline__ float ex2f_(float x) {
    float y; asm("ex2.approx.ftz.f32 %0, %1;" : "=f"(y) : "f"(x)); return y;
}
__device__ __forceinline__ float sqrtf_(float x) {
    float y; asm("sqrt.approx.ftz.f32 %0, %1;" : "=f"(y) : "f"(x)); return y;
}
__device__ __forceinline__ bool mask_at(const void* m, int idx, int isByte) {
    if (isByte) return ((const unsigned char*)m)[idx] != 0;
    return ((const int*)m)[idx] != 0;
}

// One softmax term; used by loop AND diagonal correction -> bit-identical.
__device__ __forceinline__ float pair_term(float2 AC, float4 P, float cbw,
                                           float pxi, float pyi, float pzi,
                                           float sqi, float nrm) {
    float t = fmaf(P.z, pzi, P.w);
    t = fmaf(P.y, pyi, t);
    t = fmaf(P.x, pxi, t);
    float d2 = fmaxf(sqi + t, 1e-12f);
    float dist = sqrtf_(d2);
    float s = fmaf(nrm, AC.x, AC.y);
    s = fmaf(cbw, dist, s);
    return ex2f_(s);
}

// ---------------------------------------------------------------------------
__global__ __launch_bounds__(1024)
void setup_kernel(const unsigned int* __restrict__ nm,
                  const float* __restrict__ lin1_w,
                  const float* __restrict__ lin1_b,
                  const float* __restrict__ wp,
                  const float* __restrict__ bp,
                  const float* __restrict__ wd,
                  const float* __restrict__ wc) {
    int any = 0;
    for (int k = threadIdx.x; k < (Bb * Nn) / 4; k += 1024)
        if (nm[k] > 1u) any = 1;
    int r = __syncthreads_or(any);
    if (threadIdx.x == 0) g_mask_byte = r ? 1 : 0;

    if (threadIdx.x < 32) {
        const float L2E = 1.4426950408889634f;
        int lane = threadIdx.x;
        float u0 = 0.f, u1 = 0.f, u2 = 0.f, au = 0.f;
        float v0 = 0.f, v1 = 0.f, v2 = 0.f, av = 0.f, kd = 0.f;
        for (int h = lane; h < Hh; h += 32) {
            float w1h = wc[h];
            float w2h = wc[Hh + h];
            float a = lin1_w[h] * w1h;
            float c = lin1_b[h] * w1h;
            float wp0 = wp[h * 3 + 0], wp1 = wp[h * 3 + 1], wp2 = wp[h * 3 + 2];
            u0 = fmaf(a, wp0, u0); u1 = fmaf(a, wp1, u1); u2 = fmaf(a, wp2, u2);
            au = fmaf(a, bp[h], au);
            v0 = fmaf(c, wp0, v0); v1 = fmaf(c, wp1, v1); v2 = fmaf(c, wp2, v2);
            av = fmaf(c, bp[h], av);
            kd = fmaf(wd[h], w2h, kd);
        }
        #pragma unroll
        for (int o = 16; o > 0; o >>= 1) {
            u0 += __shfl_xor_sync(0xFFFFFFFFu, u0, o);
            u1 += __shfl_xor_sync(0xFFFFFFFFu, u1, o);
            u2 += __shfl_xor_sync(0xFFFFFFFFu, u2, o);
            au += __shfl_xor_sync(0xFFFFFFFFu, au, o);
            v0 += __shfl_xor_sync(0xFFFFFFFFu, v0, o);
            v1 += __shfl_xor_sync(0xFFFFFFFFu, v1, o);
            v2 += __shfl_xor_sync(0xFFFFFFFFu, v2, o);
            av += __shfl_xor_sync(0xFFFFFFFFu, av, o);
            kd += __shfl_xor_sync(0xFFFFFFFFu, kd, o);
        }
        if (lane == 0) {
            g_prm[0] = u0 * L2E; g_prm[1] = u1 * L2E; g_prm[2] = u2 * L2E; g_prm[3] = au * L2E;
            g_prm[4] = v0 * L2E; g_prm[5] = v1 * L2E; g_prm[6] = v2 * L2E; g_prm[7] = av * L2E;
            g_prm[8] = kd * L2E;
        }
    }
}

// ---------------------------------------------------------------------------
// j-axis is reordered pharma-first within each batch (deterministic scan).
// Pharma-row warps run the distance path only over the pharma-j prefix.
// ---------------------------------------------------------------------------
__global__ __launch_bounds__(THREADS, 4)
void attn_kernel(const float* __restrict__ pos,
                 const void* __restrict__ node_mask,
                 const float* __restrict__ p,
                 const void* __restrict__ pharma,
                 const float* __restrict__ lin1_w,
                 const float* __restrict__ lin1_b,
                 const float* __restrict__ lin2_w,
                 const float* __restrict__ lin2_b,
                 float* __restrict__ out) {
    __shared__ float2 s_AC[Nn];
    __shared__ float4 s_P[Nn];
    __shared__ float4 s_Q[Nn];
    __shared__ int    s_jpos[Nn];       // orig j -> reordered pos
    __shared__ int    s_chk[32];        // per-chunk pharma counts / prefix
    __shared__ int    s_npj;            // pharma-j count in batch
    __shared__ int    s_rows[ROWS_PER_BLOCK];
    __shared__ int    s_np;             // pharma-row count in block
    __shared__ float  s_red[WARPS];
    __shared__ float  s_mean[3];
    __shared__ int    s_tk;

    const int b = blockIdx.y;
    const int tid = threadIdx.x;
    const int w = tid >> 5;
    const int lane = tid & 31;
    const int isB = g_mask_byte;

    const float u0 = g_prm[0], u1 = g_prm[1], u2 = g_prm[2], au = g_prm[3];
    const float v0 = g_prm[4], v1 = g_prm[5], v2 = g_prm[6], av = g_prm[7];
    const float kdL = g_prm[8];

    const float* posb = pos + (size_t)b * Nn * 3;
    const float* pb   = p   + (size_t)b * Nn * 3;

    // ---- pass 1: per-chunk pharma counts (chunk = 32 consecutive j)
    #pragma unroll
    for (int k = 0; k < Nn / THREADS; k++) {
        int j = k * THREADS + tid;
        bool ph = mask_at(pharma, b * Nn + j, isB);
        unsigned m = __ballot_sync(0xFFFFFFFFu, ph);
        if (lane == 0) s_chk[k * WARPS + w] = __popc(m);
    }
    __syncthreads();
    // exclusive prefix over 32 chunks (warp 0)
    if (tid < 32) {
        int v = s_chk[tid];
        int incl = v;
        #pragma unroll
        for (int o = 1; o < 32; o <<= 1) {
            int t = __shfl_up_sync(0xFFFFFFFFu, incl, o);
            if (lane >= o) incl += t;
        }
        s_chk[tid] = incl - v;                   // exclusive
        if (tid == 31) s_npj = incl;             // total pharma-j
    }
    __syncthreads();
    const int npj = s_npj;

    // ---- pass 2: compute j-data, scatter to reordered position
    #pragma unroll
    for (int k = 0; k < Nn / THREADS; k++) {
        int j = k * THREADS + tid;
        bool ph = mask_at(pharma, b * Nn + j, isB);
        unsigned m = __ballot_sync(0xFFFFFFFFu, ph);
        unsigned below = m & ((lane == 31) ? 0x7FFFFFFFu : ((1u << lane) - 1u));
        int c = k * WARPS + w;
        int phOff = s_chk[c];
        int pos_;
        if (ph) pos_ = phOff + __popc(below);
        else    pos_ = npj + (c * 32 - phOff) + (lane - __popc(below));
        s_jpos[j] = pos_;

        float qx = posb[j * 3 + 0], qy = posb[j * 3 + 1], qz = posb[j * 3 + 2];
        float A = fmaf(qx, u0, fmaf(qy, u1, fmaf(qz, u2, au)));
        float C = fmaf(qx, v0, fmaf(qy, v1, fmaf(qz, v2, av)));
        s_AC[pos_] = make_float2(A, C);
        float px = pb[j * 3 + 0], py = pb[j * 3 + 1], pz = pb[j * 3 + 2];
        float sq = fmaf(px, px, fmaf(py, py, pz * pz));
        s_P[pos_] = make_float4(-2.f * px, -2.f * py, -2.f * pz, sq);
        s_Q[pos_] = make_float4(qx, qy, qz, ph ? kdL : 0.f);
    }
    __syncthreads();

    // ---- partition this block's 32 rows: pharma rows first
    if (tid < 32) {
        int row = blockIdx.x * ROWS_PER_BLOCK + tid;
        bool ph = (s_jpos[row] < npj);
        unsigned m = __ballot_sync(0xFFFFFFFFu, ph);
        int np = __popc(m);
        unsigned below = m & ((tid == 31) ? 0x7FFFFFFFu : ((1u << tid) - 1u));
        int pos_;
        if (ph) pos_ = __popc(below);
        else    pos_ = np + (tid - __popc(below));
        s_rows[pos_] = row;
        if (tid == 0) s_np = np;
    }
    __syncthreads();

    const int np = s_np;
    const int base = w * RPT;
    const int cls = (base + RPT <= np) ? 0 : ((base >= np) ? 2 : 1);
    const int njc = (npj + 31) >> 5;   // chunks needing the distance path

    float pxi[RPT], pyi[RPT], pzi[RPT], sqi[RPT], nrm[RPT], rgf[RPT];
    float sum[RPT], cx[RPT], cy[RPT], cz[RPT];
    #pragma unroll
    for (int r = 0; r < RPT; r++) {
        int pi = s_jpos[s_rows[base + r]];
        float4 P = s_P[pi];
        pxi[r] = -0.5f * P.x; pyi[r] = -0.5f * P.y; pzi[r] = -0.5f * P.z;
        sqi[r] = P.w;
        float4 Q = s_Q[pi];
        nrm[r] = sqrtf(fmaf(Q.x, Q.x, fmaf(Q.y, Q.y, Q.z * Q.z)));
        rgf[r] = (base + r < np) ? 1.f : 0.f;
        sum[r] = 0.f; cx[r] = 0.f; cy[r] = 0.f; cz[r] = 0.f;
    }

    if (cls == 0) {
        #pragma unroll 4
        for (int jj = 0; jj < njc; jj++) {           // distance segment
            const int j = jj * 32 + lane;
            const float2 AC = s_AC[j];
            const float4 P  = s_P[j];
            const float4 Q  = s_Q[j];
            #pragma unroll
            for (int r = 0; r < RPT; r++) {
                float e = pair_term(AC, P, Q.w, pxi[r], pyi[r], pzi[r], sqi[r], nrm[r]);
                sum[r] += e;
                cx[r] = fmaf(e, Q.x, cx[r]);
                cy[r] = fmaf(e, Q.y, cy[r]);
                cz[r] = fmaf(e, Q.z, cz[r]);
            }
        }
        #pragma unroll 4
        for (int jj = njc; jj < Nn / 32; jj++) {     // cheap segment
            const int j = jj * 32 + lane;
            const float2 AC = s_AC[j];
            const float4 Q  = s_Q[j];
            #pragma unroll
            for (int r = 0; r < RPT; r++) {
                float e = ex2f_(fmaf(nrm[r], AC.x, AC.y));
                sum[r] += e;
                cx[r] = fmaf(e, Q.x, cx[r]);
                cy[r] = fmaf(e, Q.y, cy[r]);
                cz[r] = fmaf(e, Q.z, cz[r]);
            }
        }
    } else if (cls == 2) {
        #pragma unroll 4
        for (int jj = 0; jj < Nn / 32; jj++) {
            const int j = jj * 32 + lane;
            const float2 AC = s_AC[j];
            const float4 Q  = s_Q[j];
            #pragma unroll
            for (int r = 0; r < RPT; r++) {
                float e = ex2f_(fmaf(nrm[r], AC.x, AC.y));
                sum[r] += e;
                cx[r] = fmaf(e, Q.x, cx[r]);
                cy[r] = fmaf(e, Q.y, cy[r]);
                cz[r] = fmaf(e, Q.z, cz[r]);
            }
        }
    } else {
        #pragma unroll 4
        for (int jj = 0; jj < njc; jj++) {
            const int j = jj * 32 + lane;
            const float2 AC = s_AC[j];
            const float4 P  = s_P[j];
            const float4 Q  = s_Q[j];
            #pragma unroll
            for (int r = 0; r < RPT; r++) {
                float cb = Q.w * rgf[r];
                float e = pair_term(AC, P, cb, pxi[r], pyi[r], pzi[r], sqi[r], nrm[r]);
                sum[r] += e;
                cx[r] = fmaf(e, Q.x, cx[r]);
                cy[r] = fmaf(e, Q.y, cy[r]);
                cz[r] = fmaf(e, Q.z, cz[r]);
            }
        }
        #pragma unroll 4
        for (int jj = njc; jj < Nn / 32; jj++) {
            const int j = jj * 32 + lane;
            const float2 AC = s_AC[j];
            const float4 Q  = s_Q[j];
            #pragma unroll
            for (int r = 0; r < RPT; r++) {
                float e = ex2f_(fmaf(nrm[r], AC.x, AC.y));
                sum[r] += e;
                cx[r] = fmaf(e, Q.x, cx[r]);
                cy[r] = fmaf(e, Q.y, cy[r]);
                cz[r] = fmaf(e, Q.z, cz[r]);
            }
        }
    }

    // per-row MLP: h outer so weight loads are shared across rows
    float nnv[RPT];
    #pragma unroll
    for (int r = 0; r < RPT; r++) nnv[r] = 0.f;
    #pragma unroll
    for (int k = 0; k < Hh / 32; k++) {
        int h = k * 32 + lane;
        float w1 = lin1_w[h], b1 = lin1_b[h], w2 = lin2_w[h];
        #pragma unroll
        for (int r = 0; r < RPT; r++)
            nnv[r] = fmaf(fmaxf(fmaf(nrm[r], w1, b1), 0.f), w2, nnv[r]);
    }

    #pragma unroll
    for (int r = 0; r < RPT; r++) {
        #pragma unroll
        for (int o = 16; o > 0; o >>= 1) {
            sum[r] += __shfl_xor_sync(0xFFFFFFFFu, sum[r], o);
            cx[r]  += __shfl_xor_sync(0xFFFFFFFFu, cx[r], o);
            cy[r]  += __shfl_xor_sync(0xFFFFFFFFu, cy[r], o);
            cz[r]  += __shfl_xor_sync(0xFFFFFFFFu, cz[r], o);
            nnv[r] += __shfl_xor_sync(0xFFFFFFFFu, nnv[r], o);
        }
    }

    const float l2b = lin2_b[0];
    #pragma unroll
    for (int r = 0; r < RPT; r++) {
        if (lane == r) {
            int i = s_rows[base + r];
            int gi = b * Nn + i;
            int pi = s_jpos[i];
            float4 Q = s_Q[pi];
            float S = sum[r], X = cx[r], Y = cy[r], Z = cz[r];
            if (cls != 2) {
                // remove loop's j==i term, add dist-free term (bit-exact redo)
                float cbw = Q.w * rgf[r];
                float e_wrong = pair_term(s_AC[pi], s_P[pi], cbw,
                                          pxi[r], pyi[r], pzi[r], sqi[r], nrm[r]);
                float e_right = ex2f_(fmaf(nrm[r], s_AC[pi].x, s_AC[pi].y));
                float d = e_right - e_wrong;
                S += d; X = fmaf(d, Q.x, X); Y = fmaf(d, Q.y, Y); Z = fmaf(d, Q.z, Z);
            }
            float f = mask_at(node_mask, gi, isB)
                        ? (nnv[r] + l2b) / (S * (nrm[r] + 1e-5f)) : 0.f;
            out[gi * 3 + 0] = Q.x * X * f;
            out[gi * 3 + 1] = Q.y * Y * f;
            out[gi * 3 + 2] = Q.z * Z * f;
        }
    }

    // fused per-batch mean subtraction (last block of batch)
    __threadfence();
    __syncthreads();
    if (tid == 0) s_tk = atomicAdd(&g_cnt[b], 1);
    __syncthreads();
    if (s_tk == GRIDX - 1) {
        __threadfence();
        float ax = 0.f, ay = 0.f, az = 0.f;
        for (int n = tid; n < Nn; n += THREADS) {
            const float* o = out + ((size_t)b * Nn + n) * 3;
            ax += o[0]; ay += o[1]; az += o[2];
        }
        float* comps[3] = {&ax, &ay, &az};
        #pragma unroll
        for (int c = 0; c < 3; c++) {
            float v = *comps[c];
            #pragma unroll
            for (int o = 16; o > 0; o >>= 1) v += __shfl_xor_sync(0xFFFFFFFFu, v, o);
            if (lane == 0) s_red[w] = v;
            __syncthreads();
            if (tid == 0) {
                float t = 0.f;
                #pragma unroll
                for (int k = 0; k < WARPS; k++) t += s_red[k];
                s_mean[c] = t * (1.f / Nn);
            }
            __syncthreads();
        }
        float mx = s_mean[0], my = s_mean[1], mz = s_mean[2];
        for (int n = tid; n < Nn; n += THREADS) {
            float* o = out + ((size_t)b * Nn + n) * 3;
            o[0] -= mx; o[1] -= my; o[2] -= mz;
        }
        if (tid == 0) atomicExch(&g_cnt[b], 0);
    }
}

extern "C" void kernel_launch(void* const* d_in, const int* in_sizes, int n_in,
                              void* d_out, int out_size) {
    const float* pos       = (const float*)d_in[0];
    const void*  node_mask = d_in[1];
    const float* p         = (const float*)d_in[2];
    const void*  pharma    = d_in[3];
    const float* lin1_w    = (const float*)d_in[4];
    const float* lin1_b    = (const float*)d_in[5];
    const float* lin2_w    = (const float*)d_in[6];
    const float* lin2_b    = (const float*)d_in[7];
    const float* wp        = (const float*)d_in[8];
    const float* bp        = (const float*)d_in[9];
    const float* wd        = (const float*)d_in[10];
    const float* wc        = (const float*)d_in[12];

    setup_kernel<<<1, 1024>>>((const unsigned int*)node_mask,
                              lin1_w, lin1_b, wp, bp, wd, wc);

    dim3 grid(GRIDX, Bb);
    attn_kernel<<<grid, THREADS>>>(pos, node_mask, p, pharma,
                                   lin1_w, lin1_b, lin2_w, lin2_b,
                                   (float*)d_out);
}